// round 15
// baseline (speedup 1.0000x reference)
#include <cuda_runtime.h>
#include <cuda_fp16.h>

#define N_NODES 131072
#define KNBR    27
#define FIN     3
#define FOUT    32
#define EPS     1e-5f

// ---------------- scratch (static device arrays: no allocation) ----------------
// g_h permuted fp16 rows, 64B/row = 8 groups x 8B, position p = c*2 + tk.
// Group (tk,c) holds halves {16tk+2c, 16tk+2c+1, 16tk+2c+8, 16tk+2c+9}.
__device__ __align__(16) unsigned long long g_h[(size_t)N_NODES * 8];   // 8 MB
__device__ __align__(16) float4 g_xp[N_NODES];                          // 2 MB
// w2 packed fp16: [k][o][p], p = c*2 + tk  (SAME p-order as g_h rows)
__device__ __align__(16) unsigned long long g_w2p[KNBR * FOUT * 8];     // 55 KB

// ---------------- helpers -------------------------------------------------------
__device__ __forceinline__ void ffma2(unsigned long long& d,
                                      unsigned long long a,
                                      unsigned long long b) {
    asm volatile("fma.rn.f32x2 %0, %1, %2, %0;" : "+l"(d) : "l"(a), "l"(b));
}
__device__ __forceinline__ unsigned long long dup2(float x) {
    unsigned long long r;
    asm("mov.b64 %0, {%1, %1};" : "=l"(r) : "f"(x));
    return r;
}
union U64F2 { unsigned long long u; float2 f; };

__device__ __forceinline__ void hmma(float* d,
                                     unsigned long long aL,
                                     unsigned long long aH,
                                     unsigned long long b) {
    unsigned a0 = (unsigned)aL, a2 = (unsigned)(aL >> 32);
    unsigned a1 = (unsigned)aH, a3 = (unsigned)(aH >> 32);
    unsigned b0 = (unsigned)b,  b1 = (unsigned)(b >> 32);
    asm volatile(
        "mma.sync.aligned.m16n8k16.row.col.f32.f16.f16.f32 "
        "{%0,%1,%2,%3}, {%4,%5,%6,%7}, {%8,%9}, {%0,%1,%2,%3};\n"
        : "+f"(d[0]), "+f"(d[1]), "+f"(d[2]), "+f"(d[3])
        : "r"(a0), "r"(a1), "r"(a2), "r"(a3), "r"(b0), "r"(b1));
}
__device__ __forceinline__ unsigned long long pk64(unsigned lo, unsigned hi) {
    return ((unsigned long long)hi << 32) | lo;
}
__device__ __forceinline__ void cp_async16(unsigned saddr, const void* gaddr) {
    asm volatile("cp.async.cg.shared.global [%0], [%1], 16;\n"
                 :: "r"(saddr), "l"(gaddr));
}
__device__ __forceinline__ void cp_commit() {
    asm volatile("cp.async.commit_group;\n");
}
template <int N>
__device__ __forceinline__ void cp_wait() {
    asm volatile("cp.async.wait_group %0;\n" :: "n"(N));
}
__device__ __forceinline__ uint4 lds128(unsigned addr) {
    uint4 v;
    asm volatile("ld.shared.v4.u32 {%0,%1,%2,%3}, [%4];"
                 : "=r"(v.x), "=r"(v.y), "=r"(v.z), "=r"(v.w) : "r"(addr));
    return v;
}

// ---------------- kernel 0: pad x rows + pack w2 (p-order), one launch ---------
__global__ void prep_kernel(const float* __restrict__ x,
                            const float* __restrict__ w2) {
    int bid = blockIdx.x;
    int tid = threadIdx.x;
    if (bid < N_NODES / 256) {
        int n = bid * 256 + tid;
        float4 v;
        v.x = x[3 * (size_t)n];
        v.y = x[3 * (size_t)n + 1];
        v.z = x[3 * (size_t)n + 2];
        v.w = 0.f;
        g_xp[n] = v;
    } else {
        int t = (bid - N_NODES / 256) * 256 + tid;
        if (t >= KNBR * FOUT * 8) return;
        int p  = t & 7;            // p = c*2 + tk
        int tk = p & 1;
        int cc = p >> 1;
        int o  = (t >> 3) & 31;
        int k  = t >> 8;
        int f0 = 16 * tk + 2 * cc;
        const float* base = w2 + (size_t)k * FOUT * FOUT + o;   // stride FOUT over f
        __half2 lo = __floats2half2_rn(base[(size_t)f0 * FOUT],
                                       base[(size_t)(f0 + 1) * FOUT]);
        __half2 hi = __floats2half2_rn(base[(size_t)(f0 + 8) * FOUT],
                                       base[(size_t)(f0 + 9) * FOUT]);
        unsigned ulo = *reinterpret_cast<unsigned*>(&lo);
        unsigned uhi = *reinterpret_cast<unsigned*>(&hi);
        g_w2p[t] = pk64(ulo, uhi);
    }
}

// ---------------- kernel 1: h = silu(bn(gatherGEMM(x, w1))) -> permuted fp16 ---
// 1 node/thread, 4 CTAs/SM, nbr slice staged in smem (coalesced once).
__device__ __forceinline__ void s1_store(int n, const unsigned long long* acc,
                                         const float* sb) {
    unsigned pw[16];
    #pragma unroll
    for (int j = 0; j < 16; j++) {
        U64F2 uv; uv.u = acc[j];
        float a0 = uv.f.x + sb[2 * j];
        float a1 = uv.f.y + sb[2 * j + 1];
        a0 = a0 / (1.f + __expf(-a0));
        a1 = a1 / (1.f + __expf(-a1));
        __half2 hh = __floats2half2_rn(a0, a1);
        pw[j] = *reinterpret_cast<unsigned*>(&hh);
    }
    ulonglong2* dst = reinterpret_cast<ulonglong2*>(g_h + (size_t)n * 8);
    #pragma unroll
    for (int j = 0; j < 4; j++) {      // j = c; positions 2j (tk0), 2j+1 (tk1)
        ulonglong2 v;
        v.x = pk64(pw[j],     pw[j + 4]);
        v.y = pk64(pw[8 + j], pw[12 + j]);
        dst[j] = v;
    }
}

__global__ __launch_bounds__(256, 4) void stage1_kernel(
    const int*   __restrict__ nbr,
    const float* __restrict__ w1,
    const float* __restrict__ gamma1,
    const float* __restrict__ beta1,
    const float* __restrict__ mean1,
    const float* __restrict__ var1)
{
    __shared__ __align__(16) float wf[KNBR * FIN * FOUT];   // 10368B
    __shared__ float ssc[FOUT];
    __shared__ float sb[FOUT];
    __shared__ int   sidx[256 * KNBR];                      // 27648B

    int tid = threadIdx.x;
    if (tid < FOUT) {
        float s = gamma1[tid] * rsqrtf(var1[tid] + EPS);
        ssc[tid] = s;
        sb[tid]  = beta1[tid] - mean1[tid] * s;
    }
    // coalesced nbr slice for this CTA's 256 nodes
    {
        const int* src = nbr + (size_t)blockIdx.x * 256 * KNBR;
        #pragma unroll
        for (int i = 0; i < KNBR; i++) sidx[i * 256 + tid] = src[i * 256 + tid];
    }
    __syncthreads();
    for (int i = tid; i < KNBR * FIN * FOUT; i += 256)
        wf[i] = w1[i] * ssc[i & 31];
    __syncthreads();

    int n = blockIdx.x * 256 + tid;
    const int* myidx = sidx + tid * KNBR;

    unsigned long long acc[16];
    #pragma unroll
    for (int j = 0; j < 16; j++) acc[j] = 0ull;

    #pragma unroll 3
    for (int k = 0; k < KNBR; k++) {
        int idx = myidx[k];
        float4 xv = g_xp[idx];
        float xr[3] = {xv.x, xv.y, xv.z};
        #pragma unroll
        for (int f = 0; f < FIN; f++) {
            unsigned long long hf = dup2(xr[f]);
            const ulonglong2* wrow =
                reinterpret_cast<const ulonglong2*>(wf + (k * FIN + f) * FOUT);
            #pragma unroll
            for (int j = 0; j < 8; j++) {
                ulonglong2 w = wrow[j];
                ffma2(acc[2 * j],     hf, w.x);
                ffma2(acc[2 * j + 1], hf, w.y);
            }
        }
    }
    s1_store(n, acc, sb);
}

// ---------------- stage-2 inner compute (B via LDS.128, p-order pack) ----------
__device__ __forceinline__ void mma_step(
    float acc[2][4][4],
    uint4 r0, uint4 r1, uint4 r2, uint4 r3,
    unsigned wkAddr, int gid)
{
    unsigned long long aL0[2] = { pk64(r0.x, r0.y), pk64(r0.z, r0.w) };
    unsigned long long aH0[2] = { pk64(r1.x, r1.y), pk64(r1.z, r1.w) };
    unsigned long long aL1[2] = { pk64(r2.x, r2.y), pk64(r2.z, r2.w) };
    unsigned long long aH1[2] = { pk64(r3.x, r3.y), pk64(r3.z, r3.w) };

    #pragma unroll
    for (int tn = 0; tn < 4; tn++) {
        // row o = tn*8+gid, 64B/row; lane offset c*16 is folded into wkAddr.
        uint4 bq = lds128(wkAddr + (unsigned)((tn * 8 + gid) * 64));
        unsigned long long b0 = pk64(bq.x, bq.y);   // tk = 0
        unsigned long long b1 = pk64(bq.z, bq.w);   // tk = 1
        hmma(acc[0][tn], aL0[0], aH0[0], b0);
        hmma(acc[1][tn], aL1[0], aH1[0], b0);
        hmma(acc[0][tn], aL0[1], aH0[1], b1);
        hmma(acc[1][tn], aL1[1], aH1[1], b1);
    }
}

// ---------------- kernel 2: cp.async 3-stage pipelined gather-MMA --------------
// (R8 passing structure: dynamic k-loop, register idx prefetch, rotating stage)
#define W2S_BYTES  (KNBR * FOUT * 8 * 8)          // 55296
#define ZWB_BYTES  ((FIN * FOUT + FOUT) * 4)      // 512
#define A_OFF      (W2S_BYTES + ZWB_BYTES)        // 55808
#define A_WARP     (3 * 2048)                     // 3 stages x 2KB
#define SMEM_TOT   (A_OFF + 8 * A_WARP)           // 104960

__global__ __launch_bounds__(256, 2) void stage2_mma(
    const int*   __restrict__ nbr,
    const float* __restrict__ zf,
    const float* __restrict__ mw,
    const float* __restrict__ mb,
    const float* __restrict__ mg,
    const float* __restrict__ mbeta,
    const float* __restrict__ mmean,
    const float* __restrict__ mvar,
    float* __restrict__ out, size_t off2)
{
    extern __shared__ unsigned char smemRaw[];
    unsigned long long* w2s = reinterpret_cast<unsigned long long*>(smemRaw);
    float* zw = reinterpret_cast<float*>(smemRaw + W2S_BYTES);
    float* zb = zw + FIN * FOUT;

    int tid = threadIdx.x;
    if (tid < FOUT) {
        float s = mg[tid] * rsqrtf(mvar[tid] + EPS);
        zb[tid] = (mb[tid] - mmean[tid]) * s + mbeta[tid];
        #pragma unroll
        for (int f = 0; f < FIN; f++)
            zw[f * FOUT + tid] = mw[f * FOUT + tid] * s;
    }
    {
        const ulonglong2* src = reinterpret_cast<const ulonglong2*>(g_w2p);
        ulonglong2* dst = reinterpret_cast<ulonglong2*>(w2s);
        for (int i = tid; i < KNBR * FOUT * 4; i += 256) dst[i] = src[i];
    }
    __syncthreads();

    int warp = tid >> 5, lane = tid & 31;
    int gid = lane >> 2, c = lane & 3;
    int nbase = (blockIdx.x * 8 + warp) * 32;

    const int* np0 = nbr + (size_t)(nbase + gid)      * KNBR;
    const int* np1 = nbr + (size_t)(nbase + 8 + gid)  * KNBR;
    const int* np2 = nbr + (size_t)(nbase + 16 + gid) * KNBR;
    const int* np3 = nbr + (size_t)(nbase + 24 + gid) * KNBR;

    float acc[2][4][4];
    #pragma unroll
    for (int t = 0; t < 2; t++)
        #pragma unroll
        for (int tn = 0; tn < 4; tn++)
            #pragma unroll
            for (int j = 0; j < 4; j++) acc[t][tn][j] = 0.f;

    unsigned smemSh = (unsigned)__cvta_generic_to_shared(smemRaw);
    unsigned aBase  = smemSh + A_OFF + warp * A_WARP
                    + (unsigned)(gid * 64 + c * 16);
    unsigned wkAddr = smemSh + (unsigned)(c * 16);   // w2s at smem offset 0
    const char* hB  = reinterpret_cast<const char*>(g_h);
    unsigned cOff   = (unsigned)c * 16u;

    // prologue: stages for k = 0,1,2
    #pragma unroll
    for (int s = 0; s < 3; s++) {
        cp_async16(aBase + s * 2048 + 0,    hB + (size_t)(unsigned)np0[s] * 64 + cOff);
        cp_async16(aBase + s * 2048 + 512,  hB + (size_t)(unsigned)np1[s] * 64 + cOff);
        cp_async16(aBase + s * 2048 + 1024, hB + (size_t)(unsigned)np2[s] * 64 + cOff);
        cp_async16(aBase + s * 2048 + 1536, hB + (size_t)(unsigned)np3[s] * 64 + cOff);
        cp_commit();
    }
    // idx for k+3 (consumed at iter k), preloaded one iteration ahead
    int ia0 = np0[3], ia1 = np1[3], ia2 = np2[3], ia3 = np3[3];

    unsigned sOff = 0;

    #pragma unroll 1
    for (int k = 0; k < KNBR - 3; k++) {
        cp_wait<2>();                           // stage k ready
        uint4 r0 = lds128(aBase + sOff + 0);
        uint4 r1 = lds128(aBase + sOff + 512);
        uint4 r2 = lds128(aBase + sOff + 1024);
        uint4 r3 = lds128(aBase + sOff + 1536);
        mma_step(acc, r0, r1, r2, r3, wkAddr, gid);
        wkAddr += 2048;

        // refill same stage with k+3
        cp_async16(aBase + sOff + 0,    hB + (size_t)(unsigned)ia0 * 64 + cOff);
        cp_async16(aBase + sOff + 512,  hB + (size_t)(unsigned)ia1 * 64 + cOff);
        cp_async16(aBase + sOff + 1024, hB + (size_t)(unsigned)ia2 * 64 + cOff);
        cp_async16(aBase + sOff + 1536, hB + (size_t)(unsigned)ia3 * 64 + cOff);
        cp_commit();

        int kn = (k + 4 < KNBR) ? k + 4 : KNBR - 1;
        ia0 = np0[kn]; ia1 = np1[kn]; ia2 = np2[kn]; ia3 = np3[kn];

        sOff = (sOff == 4096u) ? 0u : sOff + 2048u;
    }
    // tail: k = 24, 25, 26
    {
        cp_wait<2>();
        uint4 r0 = lds128(aBase + sOff), r1 = lds128(aBase + sOff + 512);
        uint4 r2 = lds128(aBase + sOff + 1024), r3 = lds128(aBase + sOff + 1536);
        mma_step(acc, r0, r1, r2, r3, wkAddr, gid); wkAddr += 2048;
        sOff = (sOff == 4096u) ? 0u : sOff + 2048u;
    }
    {
        cp_wait<1>();
        uint4 r0 = lds128(aBase + sOff), r1 = lds128(aBase + sOff + 512);
        uint4 r2 = lds128(aBase + sOff + 1024), r3 = lds128(aBase + sOff + 1536);
        mma_step(acc, r0, r1, r2, r3, wkAddr, gid); wkAddr += 2048;
        sOff = (sOff == 4096u) ? 0u : sOff + 2048u;
    }
    {
        cp_wait<0>();
        uint4 r0 = lds128(aBase + sOff), r1 = lds128(aBase + sOff + 512);
        uint4 r2 = lds128(aBase + sOff + 1024), r3 = lds128(aBase + sOff + 1536);
        mma_step(acc, r0, r1, r2, r3, wkAddr, gid);
    }

    // ---- epilogue: add relu(bn(z @ mlp_w + b)), write both output copies -----
    #pragma unroll
    for (int t = 0; t < 2; t++) {
        int nlo = nbase + t * 16 + gid;
        int nhi = nlo + 8;
        float zl0 = zf[3 * (size_t)nlo],     zl1 = zf[3 * (size_t)nlo + 1],
              zl2 = zf[3 * (size_t)nlo + 2];
        float zh0 = zf[3 * (size_t)nhi],     zh1 = zf[3 * (size_t)nhi + 1],
              zh2 = zf[3 * (size_t)nhi + 2];
        #pragma unroll
        for (int tn = 0; tn < 4; tn++) {
            int col = tn * 8 + c * 2;
            float w00 = zw[col],      w01 = zw[32 + col],  w02 = zw[64 + col];
            float w10 = zw[col + 1],  w11 = zw[33 + col],  w12 = zw[65 + col];
            float b0v = zb[col], b1v = zb[col + 1];
            float zlo0 = fmaxf(fmaf(zl0, w00, fmaf(zl1, w01, fmaf(zl2, w02, b0v))), 0.f);
            float zlo1 = fmaxf(fmaf(zl0, w10, fmaf(zl1, w11, fmaf(zl2, w12, b1v))), 0.f);
            float zhi0 = fmaxf(fmaf(zh0, w00, fmaf(zh1, w01, fmaf(zh2, w02, b0v))), 0.f);
            float zhi1 = fmaxf(fmaf(zh0, w10, fmaf(zh1, w11, fmaf(zh2, w12, b1v))), 0.f);
            float2 vlo = make_float2(acc[t][tn][0] + zlo0, acc[t][tn][1] + zlo1);
            float2 vhi = make_float2(acc[t][tn][2] + zhi0, acc[t][tn][3] + zhi1);
            *reinterpret_cast<float2*>(out + (size_t)nlo * 32 + col) = vlo;
            *reinterpret_cast<float2*>(out + (size_t)nhi * 32 + col) = vhi;
            *reinterpret_cast<float2*>(out + off2 + (size_t)nlo * 32 + col) = vlo;
            *reinterpret_cast<float2*>(out + off2 + (size_t)nhi * 32 + col) = vhi;
        }
    }
}

// ------------------------------- launcher -------------------------------------
extern "C" void kernel_launch(void* const* d_in, const int* in_sizes, int n_in,
                              void* d_out, int out_size) {
    const float* x    = (const float*)d_in[0];
    const float* zf   = (const float*)d_in[1];
    const int*   nbr  = (const int*)d_in[2];
    const float* w1   = (const float*)d_in[3];
    const float* g1   = (const float*)d_in[4];
    const float* b1   = (const float*)d_in[5];
    const float* m1   = (const float*)d_in[6];
    const float* v1   = (const float*)d_in[7];
    const float* w2   = (const float*)d_in[8];
    const float* mw   = (const float*)d_in[9];
    const float* mb   = (const float*)d_in[10];
    const float* mg   = (const float*)d_in[11];
    const float* mbt  = (const float*)d_in[12];
    const float* mm   = (const float*)d_in[13];
    const float* mv   = (const float*)d_in[14];
    float* out = (float*)d_out;

    size_t off2 = (size_t)out_size - (size_t)N_NODES * FOUT;

    int prepGrid = N_NODES / 256 + (KNBR * FOUT * 8 + 255) / 256;
    prep_kernel<<<prepGrid, 256>>>(x, w2);
    stage1_kernel<<<N_NODES / 256, 256>>>(nbr, w1, g1, b1, m1, v1);

    cudaFuncSetAttribute(stage2_mma,
                         cudaFuncAttributeMaxDynamicSharedMemorySize, SMEM_TOT);
    stage2_mma<<<N_NODES / 256, 256, SMEM_TOT>>>(
        nbr, zf, mw, mb, mg, mbt, mm, mv, out, off2);
}

// round 17
// speedup vs baseline: 1.0414x; 1.0414x over previous
#include <cuda_runtime.h>
#include <cuda_fp16.h>

#define N_NODES 131072
#define KNBR    27
#define FIN     3
#define FOUT    32
#define EPS     1e-5f

// ---------------- scratch (static device arrays: no allocation) ----------------
// g_h permuted fp16 rows, 64B/row = 8 groups x 8B, position p = c*2 + tk.
// Group (tk,c) holds halves {16tk+2c, 16tk+2c+1, 16tk+2c+8, 16tk+2c+9}.
__device__ __align__(16) unsigned long long g_h[(size_t)N_NODES * 8];   // 8 MB
__device__ __align__(16) float4 g_xp[N_NODES];                          // 2 MB
// w2 packed fp16: [k][o][p], p = c*2 + tk  (SAME p-order as g_h rows)
__device__ __align__(16) unsigned long long g_w2p[KNBR * FOUT * 8];     // 55 KB

// ---------------- helpers -------------------------------------------------------
__device__ __forceinline__ void ffma2(unsigned long long& d,
                                      unsigned long long a,
                                      unsigned long long b) {
    asm volatile("fma.rn.f32x2 %0, %1, %2, %0;" : "+l"(d) : "l"(a), "l"(b));
}
__device__ __forceinline__ unsigned long long dup2(float x) {
    unsigned long long r;
    asm("mov.b64 %0, {%1, %1};" : "=l"(r) : "f"(x));
    return r;
}
union U64F2 { unsigned long long u; float2 f; };

__device__ __forceinline__ void hmma(float* d,
                                     unsigned long long aL,
                                     unsigned long long aH,
                                     unsigned long long b) {
    unsigned a0 = (unsigned)aL, a2 = (unsigned)(aL >> 32);
    unsigned a1 = (unsigned)aH, a3 = (unsigned)(aH >> 32);
    unsigned b0 = (unsigned)b,  b1 = (unsigned)(b >> 32);
    asm volatile(
        "mma.sync.aligned.m16n8k16.row.col.f32.f16.f16.f32 "
        "{%0,%1,%2,%3}, {%4,%5,%6,%7}, {%8,%9}, {%0,%1,%2,%3};\n"
        : "+f"(d[0]), "+f"(d[1]), "+f"(d[2]), "+f"(d[3])
        : "r"(a0), "r"(a1), "r"(a2), "r"(a3), "r"(b0), "r"(b1));
}
__device__ __forceinline__ unsigned long long pk64(unsigned lo, unsigned hi) {
    return ((unsigned long long)hi << 32) | lo;
}
__device__ __forceinline__ void cp_async16(unsigned saddr, const void* gaddr) {
    asm volatile("cp.async.cg.shared.global [%0], [%1], 16;\n"
                 :: "r"(saddr), "l"(gaddr));
}
__device__ __forceinline__ void cp_commit() {
    asm volatile("cp.async.commit_group;\n");
}
template <int N>
__device__ __forceinline__ void cp_wait() {
    asm volatile("cp.async.wait_group %0;\n" :: "n"(N));
}
__device__ __forceinline__ uint4 lds128(unsigned addr) {
    uint4 v;
    asm volatile("ld.shared.v4.u32 {%0,%1,%2,%3}, [%4];"
                 : "=r"(v.x), "=r"(v.y), "=r"(v.z), "=r"(v.w) : "r"(addr));
    return v;
}

// ---------------- kernel 0: pad x rows + pack w2 (p-order), one launch ---------
__global__ void prep_kernel(const float* __restrict__ x,
                            const float* __restrict__ w2) {
    int bid = blockIdx.x;
    int tid = threadIdx.x;
    if (bid < N_NODES / 256) {
        int n = bid * 256 + tid;
        float4 v;
        v.x = x[3 * (size_t)n];
        v.y = x[3 * (size_t)n + 1];
        v.z = x[3 * (size_t)n + 2];
        v.w = 0.f;
        g_xp[n] = v;
    } else {
        int t = (bid - N_NODES / 256) * 256 + tid;
        if (t >= KNBR * FOUT * 8) return;
        int p  = t & 7;            // p = c*2 + tk
        int tk = p & 1;
        int cc = p >> 1;
        int o  = (t >> 3) & 31;
        int k  = t >> 8;
        int f0 = 16 * tk + 2 * cc;
        const float* base = w2 + (size_t)k * FOUT * FOUT + o;   // stride FOUT over f
        __half2 lo = __floats2half2_rn(base[(size_t)f0 * FOUT],
                                       base[(size_t)(f0 + 1) * FOUT]);
        __half2 hi = __floats2half2_rn(base[(size_t)(f0 + 8) * FOUT],
                                       base[(size_t)(f0 + 9) * FOUT]);
        unsigned ulo = *reinterpret_cast<unsigned*>(&lo);
        unsigned uhi = *reinterpret_cast<unsigned*>(&hi);
        g_w2p[t] = pk64(ulo, uhi);
    }
}

// ---------------- kernel 1: h = silu(bn(gatherGEMM(x, w1))) -> permuted fp16 ---
// R8-proven version: 2 nodes/thread, weight LDS shared across both nodes.
__device__ __forceinline__ void s1_store(int n, const unsigned long long* acc,
                                         const float* sb) {
    unsigned pw[16];
    #pragma unroll
    for (int j = 0; j < 16; j++) {
        U64F2 uv; uv.u = acc[j];
        float a0 = uv.f.x + sb[2 * j];
        float a1 = uv.f.y + sb[2 * j + 1];
        a0 = a0 / (1.f + __expf(-a0));
        a1 = a1 / (1.f + __expf(-a1));
        __half2 hh = __floats2half2_rn(a0, a1);
        pw[j] = *reinterpret_cast<unsigned*>(&hh);
    }
    ulonglong2* dst = reinterpret_cast<ulonglong2*>(g_h + (size_t)n * 8);
    #pragma unroll
    for (int j = 0; j < 4; j++) {      // j = c; positions 2j (tk0), 2j+1 (tk1)
        ulonglong2 v;
        v.x = pk64(pw[j],     pw[j + 4]);
        v.y = pk64(pw[8 + j], pw[12 + j]);
        dst[j] = v;
    }
}

__global__ __launch_bounds__(256) void stage1_kernel(
    const int*   __restrict__ nbr,
    const float* __restrict__ w1,
    const float* __restrict__ gamma1,
    const float* __restrict__ beta1,
    const float* __restrict__ mean1,
    const float* __restrict__ var1)
{
    __shared__ __align__(16) float wf[KNBR * FIN * FOUT];
    __shared__ float ssc[FOUT];
    __shared__ float sb[FOUT];

    int tid = threadIdx.x;
    if (tid < FOUT) {
        float s = gamma1[tid] * rsqrtf(var1[tid] + EPS);
        ssc[tid] = s;
        sb[tid]  = beta1[tid] - mean1[tid] * s;
    }
    __syncthreads();
    for (int i = tid; i < KNBR * FIN * FOUT; i += 256)
        wf[i] = w1[i] * ssc[i & 31];
    __syncthreads();

    int n0 = blockIdx.x * 512 + tid;
    int n1 = n0 + 256;
    const int* nb0 = nbr + (size_t)n0 * KNBR;
    const int* nb1 = nbr + (size_t)n1 * KNBR;

    unsigned long long acc0[16], acc1[16];
    #pragma unroll
    for (int j = 0; j < 16; j++) { acc0[j] = 0ull; acc1[j] = 0ull; }

    #pragma unroll 3
    for (int k = 0; k < KNBR; k++) {
        int i0 = nb0[k];
        int i1 = nb1[k];
        float4 xa = g_xp[i0];
        float4 xb = g_xp[i1];
        float ra[3] = {xa.x, xa.y, xa.z};
        float rb[3] = {xb.x, xb.y, xb.z};
        #pragma unroll
        for (int f = 0; f < FIN; f++) {
            unsigned long long h0 = dup2(ra[f]);
            unsigned long long h1 = dup2(rb[f]);
            const ulonglong2* wrow =
                reinterpret_cast<const ulonglong2*>(wf + (k * FIN + f) * FOUT);
            #pragma unroll
            for (int j = 0; j < 8; j++) {
                ulonglong2 w = wrow[j];
                ffma2(acc0[2 * j],     h0, w.x);
                ffma2(acc0[2 * j + 1], h0, w.y);
                ffma2(acc1[2 * j],     h1, w.x);
                ffma2(acc1[2 * j + 1], h1, w.y);
            }
        }
    }
    s1_store(n0, acc0, sb);
    s1_store(n1, acc1, sb);
}

// ---------------- stage-2 inner compute: 16 nodes/warp, 8 HMMA -----------------
__device__ __forceinline__ void mma_step16(
    float acc[4][4],
    uint4 r0, uint4 r1,                 // lo rows (gid), hi rows (8+gid)
    unsigned wkAddr, int gid)
{
    unsigned long long aL0 = pk64(r0.x, r0.y);   // lo, tk0 (a0|a2)
    unsigned long long aL1 = pk64(r0.z, r0.w);   // lo, tk1
    unsigned long long aH0 = pk64(r1.x, r1.y);   // hi, tk0 (a1|a3)
    unsigned long long aH1 = pk64(r1.z, r1.w);   // hi, tk1

    #pragma unroll
    for (int tn = 0; tn < 4; tn++) {
        uint4 bq = lds128(wkAddr + (unsigned)((tn * 8 + gid) * 64));
        unsigned long long b0 = pk64(bq.x, bq.y);   // tk = 0
        unsigned long long b1 = pk64(bq.z, bq.w);   // tk = 1
        hmma(acc[tn], aL0, aH0, b0);
        hmma(acc[tn], aL1, aH1, b1);
    }
}

// ---------------- kernel 2: cp.async 3-stage pipelined gather-MMA --------------
// 512 threads (16 warps) x 16 nodes/warp = 256 nodes/CTA; 2 CTAs/SM -> 32 warps.
#define W2S_BYTES  (KNBR * FOUT * 8 * 8)          // 55296
#define ZWB_BYTES  ((FIN * FOUT + FOUT) * 4)      // 512
#define A_OFF      (W2S_BYTES + ZWB_BYTES)        // 55808
#define A_WARP     (3 * 1024)                     // 3 stages x 1KB (16 rows x 64B)
#define SMEM_TOT   (A_OFF + 16 * A_WARP)          // 104960

__global__ __launch_bounds__(512, 2) void stage2_mma(
    const int*   __restrict__ nbr,
    const float* __restrict__ zf,
    const float* __restrict__ mw,
    const float* __restrict__ mb,
    const float* __restrict__ mg,
    const float* __restrict__ mbeta,
    const float* __restrict__ mmean,
    const float* __restrict__ mvar,
    float* __restrict__ out, size_t off2)
{
    extern __shared__ unsigned char smemRaw[];
    float* zw = reinterpret_cast<float*>(smemRaw + W2S_BYTES);
    float* zb = zw + FIN * FOUT;

    int tid = threadIdx.x;
    if (tid < FOUT) {
        float s = mg[tid] * rsqrtf(mvar[tid] + EPS);
        zb[tid] = (mb[tid] - mmean[tid]) * s + mbeta[tid];
        #pragma unroll
        for (int f = 0; f < FIN; f++)
            zw[f * FOUT + tid] = mw[f * FOUT + tid] * s;
    }
    {   // cooperative copy of packed w2 (55 KB) into smem
        const ulonglong2* src = reinterpret_cast<const ulonglong2*>(g_w2p);
        ulonglong2* dst = reinterpret_cast<ulonglong2*>(smemRaw);
        for (int i = tid; i < KNBR * FOUT * 4; i += 512) dst[i] = src[i];
    }
    __syncthreads();

    int warp = tid >> 5, lane = tid & 31;
    int gid = lane >> 2, c = lane & 3;
    int nbase = blockIdx.x * 256 + warp * 16;

    const int* np0 = nbr + (size_t)(nbase + gid)     * KNBR;   // lo rows
    const int* np1 = nbr + (size_t)(nbase + 8 + gid) * KNBR;   // hi rows

    float acc[4][4];
    #pragma unroll
    for (int tn = 0; tn < 4; tn++)
        #pragma unroll
        for (int j = 0; j < 4; j++) acc[tn][j] = 0.f;

    unsigned smemSh = (unsigned)__cvta_generic_to_shared(smemRaw);
    unsigned aBase  = smemSh + A_OFF + warp * A_WARP
                    + (unsigned)(gid * 64 + c * 16);
    unsigned wkAddr = smemSh + (unsigned)(c * 16);   // w2s at smem offset 0
    const char* hB  = reinterpret_cast<const char*>(g_h);
    unsigned cOff   = (unsigned)c * 16u;

    // prologue: stages for k = 0,1,2
    #pragma unroll
    for (int s = 0; s < 3; s++) {
        cp_async16(aBase + s * 1024 + 0,   hB + (size_t)(unsigned)np0[s] * 64 + cOff);
        cp_async16(aBase + s * 1024 + 512, hB + (size_t)(unsigned)np1[s] * 64 + cOff);
        cp_commit();
    }
    // idx for k+3 (consumed at iter k), preloaded one iteration ahead
    int ia0 = np0[3], ia1 = np1[3];

    unsigned sOff = 0;

    #pragma unroll 1
    for (int k = 0; k < KNBR - 3; k++) {
        cp_wait<2>();                           // stage k ready
        uint4 r0 = lds128(aBase + sOff + 0);
        uint4 r1 = lds128(aBase + sOff + 512);
        mma_step16(acc, r0, r1, wkAddr, gid);
        wkAddr += 2048;

        // refill same stage with k+3
        cp_async16(aBase + sOff + 0,   hB + (size_t)(unsigned)ia0 * 64 + cOff);
        cp_async16(aBase + sOff + 512, hB + (size_t)(unsigned)ia1 * 64 + cOff);
        cp_commit();

        int kn = (k + 4 < KNBR) ? k + 4 : KNBR - 1;
        ia0 = np0[kn]; ia1 = np1[kn];

        sOff = (sOff == 2048u) ? 0u : sOff + 1024u;
    }
    // tail: k = 24, 25, 26
    {
        cp_wait<2>();
        uint4 r0 = lds128(aBase + sOff), r1 = lds128(aBase + sOff + 512);
        mma_step16(acc, r0, r1, wkAddr, gid); wkAddr += 2048;
        sOff = (sOff == 2048u) ? 0u : sOff + 1024u;
    }
    {
        cp_wait<1>();
        uint4 r0 = lds128(aBase + sOff), r1 = lds128(aBase + sOff + 512);
        mma_step16(acc, r0, r1, wkAddr, gid); wkAddr += 2048;
        sOff = (sOff == 2048u) ? 0u : sOff + 1024u;
    }
    {
        cp_wait<0>();
        uint4 r0 = lds128(aBase + sOff), r1 = lds128(aBase + sOff + 512);
        mma_step16(acc, r0, r1, wkAddr, gid);
    }

    // ---- epilogue: add relu(bn(z @ mlp_w + b)), write both output copies -----
    {
        int nlo = nbase + gid;
        int nhi = nbase + 8 + gid;
        float zl0 = zf[3 * (size_t)nlo],     zl1 = zf[3 * (size_t)nlo + 1],
              zl2 = zf[3 * (size_t)nlo + 2];
        float zh0 = zf[3 * (size_t)nhi],     zh1 = zf[3 * (size_t)nhi + 1],
              zh2 = zf[3 * (size_t)nhi + 2];
        #pragma unroll
        for (int tn = 0; tn < 4; tn++) {
            int col = tn * 8 + c * 2;
            float w00 = zw[col],      w01 = zw[32 + col],  w02 = zw[64 + col];
            float w10 = zw[col + 1],  w11 = zw[33 + col],  w12 = zw[65 + col];
            float b0v = zb[col], b1v = zb[col + 1];
            float zlo0 = fmaxf(fmaf(zl0, w00, fmaf(zl1, w01, fmaf(zl2, w02, b0v))), 0.f);
            float zlo1 = fmaxf(fmaf(zl0, w10, fmaf(zl1, w11, fmaf(zl2, w12, b1v))), 0.f);
            float zhi0 = fmaxf(fmaf(zh0, w00, fmaf(zh1, w01, fmaf(zh2, w02, b0v))), 0.f);
            float zhi1 = fmaxf(fmaf(zh0, w10, fmaf(zh1, w11, fmaf(zh2, w12, b1v))), 0.f);
            float2 vlo = make_float2(acc[tn][0] + zlo0, acc[tn][1] + zlo1);
            float2 vhi = make_float2(acc[tn][2] + zhi0, acc[tn][3] + zhi1);
            *reinterpret_cast<float2*>(out + (size_t)nlo * 32 + col) = vlo;
            *reinterpret_cast<float2*>(out + (size_t)nhi * 32 + col) = vhi;
            *reinterpret_cast<float2*>(out + off2 + (size_t)nlo * 32 + col) = vlo;
            *reinterpret_cast<float2*>(out + off2 + (size_t)nhi * 32 + col) = vhi;
        }
    }
}

// ------------------------------- launcher -------------------------------------
extern "C" void kernel_launch(void* const* d_in, const int* in_sizes, int n_in,
                              void* d_out, int out_size) {
    const float* x    = (const float*)d_in[0];
    const float* zf   = (const float*)d_in[1];
    const int*   nbr  = (const int*)d_in[2];
    const float* w1   = (const float*)d_in[3];
    const float* g1   = (const float*)d_in[4];
    const float* b1   = (const float*)d_in[5];
    const float* m1   = (const float*)d_in[6];
    const float* v1   = (const float*)d_in[7];
    const float* w2   = (const float*)d_in[8];
    const float* mw   = (const float*)d_in[9];
    const float* mb   = (const float*)d_in[10];
    const float* mg   = (const float*)d_in[11];
    const float* mbt  = (const float*)d_in[12];
    const float* mm   = (const float*)d_in[13];
    const float* mv   = (const float*)d_in[14];
    float* out = (float*)d_out;

    size_t off2 = (size_t)out_size - (size_t)N_NODES * FOUT;

    int prepGrid = N_NODES / 256 + (KNBR * FOUT * 8 + 255) / 256;
    prep_kernel<<<prepGrid, 256>>>(x, w2);
    stage1_kernel<<<N_NODES / 512, 256>>>(nbr, w1, g1, b1, m1, v1);

    cudaFuncSetAttribute(stage2_mma,
                         cudaFuncAttributeMaxDynamicSharedMemorySize, SMEM_TOT);
    stage2_mma<<<N_NODES / 256, 512, SMEM_TOT>>>(
        nbr, zf, mw, mb, mg, mbt, mm, mv, out, off2);
}